// round 9
// baseline (speedup 1.0000x reference)
#include <cuda_runtime.h>
#include <cstdint>
#include <math.h>

#define TT 4096
#define HH 1024
#define DD 2752
#define NE 8
#define BM 128
#define ROWCAP (TT*2 + NE*BM)   // 9216

#define NS 3                       // pipeline stages
#define AS_F (128*32)              // 4096 floats (A tile, stride 32, XOR-swizzled)
#define BS_F (64*32)               // 2048 floats
#define GU_STAGEF (AS_F + 2*BS_F)  // 8192 floats = 32KB
#define DN_STAGEF (2*AS_F)         // 8192 floats = 32KB
#define GU_SMEMB (NS*GU_STAGEF*4)  // 98304
#define DN_SMEMB (NS*DN_STAGEF*4)  // 98304

// ---------------- scratch ----------------
__device__ int   g_offsets[NE+1];
__device__ int   g_row_token[ROWCAP];
__device__ int   g_row_tk[ROWCAP];
__device__ int   g_tok_e[TT*2];
__device__ float g_tok_w[TT*2];
__device__ float g_xc [(size_t)TT*HH];      // tf32-rounded, k-permuted x
__device__ float g_wgT[(size_t)NE*DD*HH];   // [D][H], k-permuted on H
__device__ float g_wuT[(size_t)NE*DD*HH];
__device__ float g_wdT[(size_t)NE*HH*DD];   // [H][D], k-permuted on D
__device__ float g_sgT[(size_t)DD*HH];
__device__ float g_suT[(size_t)DD*HH];
__device__ float g_sdT[(size_t)HH*DD];
__device__ float g_hid [(size_t)ROWCAP*DD]; // k-permuted on D
__device__ float g_shid[(size_t)TT*DD];     // k-permuted on D
__device__ float g_eo  [(size_t)TT*2*HH];   // plain layout

// ---------------- helpers ----------------
__device__ __forceinline__ float totf(float x){
  uint32_t u; asm("cvt.rna.tf32.f32 %0, %1;" : "=r"(u) : "f"(x));
  return __uint_as_float(u);
}
__device__ __forceinline__ int kperm(int c){ return ((c&3)<<1) | ((c>>2)&1); }  // within 8-group
__device__ __forceinline__ void cpa16(uint32_t d, const void* s){
  asm volatile("cp.async.cg.shared.global [%0], [%1], 16;"::"r"(d),"l"(s));
}
__device__ __forceinline__ void cpcommit(){ asm volatile("cp.async.commit_group;"); }
__device__ __forceinline__ void cpwait(int allow){
  if (allow <= 0) asm volatile("cp.async.wait_group 0;");
  else            asm volatile("cp.async.wait_group 1;");
}
__device__ __forceinline__ uint32_t s2u(const void* p){
  uint32_t a; asm("{ .reg .u64 t; cvta.to.shared.u64 t, %1; cvt.u32.u64 %0, t; }":"=r"(a):"l"(p)); return a;
}
__device__ __forceinline__ void mma8(float* c, const uint32_t* a, const uint32_t* b){
  asm volatile("mma.sync.aligned.m16n8k8.row.col.f32.tf32.tf32.f32 "
    "{%0,%1,%2,%3},{%4,%5,%6,%7},{%8,%9},{%0,%1,%2,%3};"
    : "+f"(c[0]),"+f"(c[1]),"+f"(c[2]),"+f"(c[3])
    : "r"(a[0]),"r"(a[1]),"r"(a[2]),"r"(a[3]),"r"(b[0]),"r"(b[1]));
}

// ---------------- route: logits/softmax/top2 + tf32-permuted x copy ----------------
__global__ void route_kernel(const float* __restrict__ x, const float* __restrict__ gw){
  int t = blockIdx.x*(blockDim.x>>5) + (threadIdx.x>>5);
  int lane = threadIdx.x & 31;
  if (t >= TT) return;
  const float* xr = x + (size_t)t*HH;
  float xs[HH/32];
  #pragma unroll
  for (int i=0;i<HH/32;i++) xs[i] = xr[lane+32*i];

  // write tf32-rounded, k-permuted copy
  int lanep = (lane & ~7) | kperm(lane & 7);
  float* xo = g_xc + (size_t)t*HH;
  #pragma unroll
  for (int i=0;i<HH/32;i++) xo[lanep + 32*i] = totf(xs[i]);

  float logit[NE];
  #pragma unroll
  for (int e=0;e<NE;e++){
    const float* w = gw + e*HH;
    float s = 0.f;
    #pragma unroll
    for (int i=0;i<HH/32;i++) s += xs[i]*w[lane+32*i];
    #pragma unroll
    for (int o=16;o;o>>=1) s += __shfl_xor_sync(0xffffffffu, s, o);
    logit[e] = s;
  }
  float m = logit[0];
  #pragma unroll
  for (int e=1;e<NE;e++) m = fmaxf(m, logit[e]);
  float p[NE], ssum = 0.f;
  #pragma unroll
  for (int e=0;e<NE;e++){ p[e] = expf(logit[e]-m); ssum += p[e]; }
  float inv = 1.f/ssum;
  #pragma unroll
  for (int e=0;e<NE;e++) p[e] *= inv;
  int i0 = 0;
  #pragma unroll
  for (int e=1;e<NE;e++) if (p[e] > p[i0]) i0 = e;
  int i1 = -1;
  #pragma unroll
  for (int e=0;e<NE;e++) if (e != i0 && (i1 < 0 || p[e] > p[i1])) i1 = e;
  float w0 = p[i0], w1 = p[i1];
  float nrm = 1.f/(w0+w1+1e-20f);
  if (lane == 0){
    g_tok_e[t*2] = i0; g_tok_e[t*2+1] = i1;
    g_tok_w[t*2] = w0*nrm; g_tok_w[t*2+1] = w1*nrm;
  }
}

// ---------------- aux: count + scan + init + assign (single block) ----------------
__global__ void aux_kernel(){
  __shared__ int sc[NE], so[NE+1], scur[NE];
  int tid = threadIdx.x;
  if (tid < NE){ sc[tid] = 0; scur[tid] = 0; }
  __syncthreads();
  for (int i = tid; i < TT*2; i += 256) atomicAdd(&sc[g_tok_e[i]], 1);
  __syncthreads();
  if (tid == 0){
    int off = 0;
    for (int e=0;e<NE;e++){ so[e]=off; off += ((sc[e]+BM-1)/BM)*BM; }
    so[NE] = off;
  }
  __syncthreads();
  if (tid <= NE) g_offsets[tid] = so[tid];
  for (int i = tid; i < ROWCAP; i += 256) g_row_token[i] = -1;
  __syncthreads();
  for (int i = tid; i < TT*2; i += 256){
    int e = g_tok_e[i];
    int pos = atomicAdd(&scur[e], 1);
    int row = so[e] + pos;
    g_row_token[row] = i>>1;
    g_row_tk[row] = i;
  }
}

// ---------------- fused weight transpose + tf32 round + k-permute ----------------
__global__ void transpose_all(const float* __restrict__ wg, const float* __restrict__ wu,
                              const float* __restrict__ wd, const float* __restrict__ sg,
                              const float* __restrict__ su, const float* __restrict__ sd){
  int z = blockIdx.z;
  const float* src; float* dst; int R, C;
  if (z < 8)       { src = wg + (size_t)z*HH*DD;      dst = g_wgT + (size_t)z*DD*HH;      R=HH; C=DD; }
  else if (z < 16) { src = wu + (size_t)(z-8)*HH*DD;  dst = g_wuT + (size_t)(z-8)*DD*HH;  R=HH; C=DD; }
  else if (z < 24) { src = wd + (size_t)(z-16)*DD*HH; dst = g_wdT + (size_t)(z-16)*HH*DD; R=DD; C=HH; }
  else if (z==24)  { src = sg; dst = g_sgT; R=HH; C=DD; }
  else if (z==25)  { src = su; dst = g_suT; R=HH; C=DD; }
  else             { src = sd; dst = g_sdT; R=DD; C=HH; }
  if (blockIdx.x*32 >= C || blockIdx.y*32 >= R) return;

  __shared__ float t[32][33];
  int x = blockIdx.x*32 + threadIdx.x;
  int y0 = blockIdx.y*32;
  #pragma unroll
  for (int j=0;j<32;j+=8)
    t[threadIdx.y+j][threadIdx.x] = src[(size_t)(y0+threadIdx.y+j)*C + x];
  __syncthreads();
  int xxl = blockIdx.y*32 + threadIdx.x;            // logical k index
  int xx  = (xxl & ~7) | kperm(xxl & 7);            // physical (k-permuted)
  int yy0 = blockIdx.x*32;
  #pragma unroll
  for (int j=0;j<32;j+=8)
    dst[(size_t)(yy0+threadIdx.y+j)*R + xx] = totf(t[threadIdx.x][threadIdx.y+j]);
}

// ---------------- gate+up GEMM: 128x64 tile, dual-B, fused silu ----------------
template<bool ROUTED>
__global__ void __launch_bounds__(256,2) gu_mma(){
  extern __shared__ float sm[];
  __shared__ int rtok[BM];
  const int tid = threadIdx.x, lane = tid&31, wid = tid>>5;
  const int wr = wid>>1, wc = wid&1;
  const int gr = lane>>2, gc = lane&3;
  const int row0 = blockIdx.y*BM, n0 = blockIdx.x*64;
  if (ROUTED && row0 >= g_offsets[NE]) return;

  const float *Wg, *Wu; float* Out;
  if (ROUTED){
    int e = 0;
    #pragma unroll
    for (int i=1;i<NE;i++) if (row0 >= g_offsets[i]) e = i;
    Wg = g_wgT + (size_t)e*DD*HH;
    Wu = g_wuT + (size_t)e*DD*HH;
    Out = g_hid;
  } else { Wg = g_sgT; Wu = g_suT; Out = g_shid; }

  if (tid < BM){
    int t = ROUTED ? g_row_token[row0+tid] : (row0+tid);
    rtok[tid] = t < 0 ? 0 : t;
  }
  __syncthreads();

  const int NCH = HH/32;   // 32
  auto ld = [&](int c, int s){
    float* S = sm + s*GU_STAGEF;
    uint32_t sA = s2u(S);
    uint32_t sG = s2u(S + AS_F);
    uint32_t sU = s2u(S + AS_F + BS_F);
    int k0 = c*32;
    #pragma unroll
    for (int j=0;j<4;j++){
      int q = tid + 256*j, r = q>>3, sg = q&7;
      cpa16(sA + r*128 + 16*(sg ^ ((r&3)<<1)), g_xc + (size_t)rtok[r]*HH + k0 + sg*4);
    }
    #pragma unroll
    for (int j=0;j<2;j++){
      int q = tid + 256*j, r = q>>3, sg = q&7;
      uint32_t so = r*128 + 16*(sg ^ ((r&3)<<1));
      cpa16(sG + so, Wg + (size_t)(n0+r)*HH + k0 + sg*4);
      cpa16(sU + so, Wu + (size_t)(n0+r)*HH + k0 + sg*4);
    }
    cpcommit();
  };
  ld(0,0); ld(1,1);

  float accg[2][4][4], accu[2][4][4];
  #pragma unroll
  for (int a=0;a<2;a++)
    #pragma unroll
    for (int b=0;b<4;b++)
      #pragma unroll
      for (int d=0;d<4;d++){ accg[a][b][d]=0.f; accu[a][b][d]=0.f; }

  for (int c=0;c<NCH;c++){
    cpwait(NCH-1-c < 1 ? 0 : 1);
    __syncthreads();
    if (c+2 < NCH) ld(c+2, (c+2)%NS);
    const float* S  = sm + (c%NS)*GU_STAGEF;
    const float* As = S;
    const float* Bg = S + AS_F;
    const float* Bu = S + AS_F + BS_F;
    #pragma unroll
    for (int ks=0;ks<4;ks++){
      int kb = 4*((2*ks + (gc>>1)) ^ ((gr&3)<<1)) + 2*(gc&1);
      uint32_t a[2][4];
      #pragma unroll
      for (int mt=0;mt<2;mt++){
        int r0 = wr*32 + mt*16;
        float2 lo = *(const float2*)(As + (r0+gr  )*32 + kb);
        float2 hi = *(const float2*)(As + (r0+gr+8)*32 + kb);
        a[mt][0] = __float_as_uint(lo.x);
        a[mt][1] = __float_as_uint(hi.x);
        a[mt][2] = __float_as_uint(lo.y);
        a[mt][3] = __float_as_uint(hi.y);
      }
      #pragma unroll
      for (int nt=0;nt<4;nt++){
        int n = wc*32 + nt*8 + gr;
        float2 vg = *(const float2*)(Bg + n*32 + kb);
        float2 vu = *(const float2*)(Bu + n*32 + kb);
        uint32_t bg[2] = { __float_as_uint(vg.x), __float_as_uint(vg.y) };
        uint32_t bu[2] = { __float_as_uint(vu.x), __float_as_uint(vu.y) };
        mma8(accg[0][nt], a[0], bg);
        mma8(accg[1][nt], a[1], bg);
        mma8(accu[0][nt], a[0], bu);
        mma8(accu[1][nt], a[1], bu);
      }
    }
  }

  // epilogue: silu(g)*u, tf32-round, store with D-permutation (feeds dn GEMM K)
  const int p0 = kperm(2*gc), p1 = kperm(2*gc+1);
  #pragma unroll
  for (int mt=0;mt<2;mt++)
    #pragma unroll
    for (int nt=0;nt<4;nt++){
      int r  = row0 + wr*32 + mt*16 + gr;
      int cb = n0 + wc*32 + nt*8;
      float g0 = accg[mt][nt][0], u0 = accu[mt][nt][0];
      float g1 = accg[mt][nt][1], u1 = accu[mt][nt][1];
      float g2 = accg[mt][nt][2], u2 = accu[mt][nt][2];
      float g3 = accg[mt][nt][3], u3 = accu[mt][nt][3];
      float* o0 = Out + (size_t)r*DD + cb;
      o0[p0] = totf(g0/(1.f+expf(-g0))*u0);
      o0[p1] = totf(g1/(1.f+expf(-g1))*u1);
      float* o1 = Out + (size_t)(r+8)*DD + cb;
      o1[p0] = totf(g2/(1.f+expf(-g2))*u2);
      o1[p1] = totf(g3/(1.f+expf(-g3))*u3);
    }
}

// ---------------- down GEMM: 128x128 tile ----------------
template<int MODE>
__global__ void __launch_bounds__(256,2) dn_mma(float* __restrict__ OutTok){
  extern __shared__ float sm[];
  __shared__ int s_tk[BM];
  const int tid = threadIdx.x, lane = tid&31, wid = tid>>5;
  const int wr = wid>>1, wc = wid&1;
  const int gr = lane>>2, gc = lane&3;
  const int row0 = blockIdx.y*BM, n0 = blockIdx.x*128;
  if (MODE==0 && row0 >= g_offsets[NE]) return;

  const float *A, *Wd;
  if (MODE == 0){
    int e = 0;
    #pragma unroll
    for (int i=1;i<NE;i++) if (row0 >= g_offsets[i]) e = i;
    Wd = g_wdT + (size_t)e*HH*DD;
    A = g_hid;
  } else { Wd = g_sdT; A = g_shid; }

  if (tid < BM)
    s_tk[tid] = (MODE==0) ? ((g_row_token[row0+tid] < 0) ? -1 : g_row_tk[row0+tid]) : 0;
  __syncthreads();

  const int NCH = DD/32;   // 86
  auto ld = [&](int c, int s){
    float* S = sm + s*DN_STAGEF;
    uint32_t sA = s2u(S);
    uint32_t sB = s2u(S + AS_F);
    int k0 = c*32;
    #pragma unroll
    for (int j=0;j<4;j++){
      int q = tid + 256*j, r = q>>3, sg = q&7;
      uint32_t so = r*128 + 16*(sg ^ ((r&3)<<1));
      cpa16(sA + so, A  + (size_t)(row0+r)*DD + k0 + sg*4);
      cpa16(sB + so, Wd + (size_t)(n0 +r)*DD + k0 + sg*4);
    }
    cpcommit();
  };
  ld(0,0); ld(1,1);

  float acc[2][8][4];
  #pragma unroll
  for (int a=0;a<2;a++)
    #pragma unroll
    for (int b=0;b<8;b++)
      #pragma unroll
      for (int d=0;d<4;d++) acc[a][b][d]=0.f;

  for (int c=0;c<NCH;c++){
    cpwait(NCH-1-c < 1 ? 0 : 1);
    __syncthreads();
    if (c+2 < NCH) ld(c+2, (c+2)%NS);
    const float* S  = sm + (c%NS)*DN_STAGEF;
    const float* As = S;
    const float* Bs = S + AS_F;
    #pragma unroll
    for (int ks=0;ks<4;ks++){
      int kb = 4*((2*ks + (gc>>1)) ^ ((gr&3)<<1)) + 2*(gc&1);
      uint32_t a[2][4];
      #pragma unroll
      for (int mt=0;mt<2;mt++){
        int r0 = wr*32 + mt*16;
        float2 lo = *(const float2*)(As + (r0+gr  )*32 + kb);
        float2 hi = *(const float2*)(As + (r0+gr+8)*32 + kb);
        a[mt][0] = __float_as_uint(lo.x);
        a[mt][1] = __float_as_uint(hi.x);
        a[mt][2] = __float_as_uint(lo.y);
        a[mt][3] = __float_as_uint(hi.y);
      }
      #pragma unroll
      for (int nt=0;nt<8;nt++){
        int n = wc*64 + nt*8 + gr;
        float2 vb = *(const float2*)(Bs + n*32 + kb);
        uint32_t b[2] = { __float_as_uint(vb.x), __float_as_uint(vb.y) };
        mma8(acc[0][nt], a[0], b);
        mma8(acc[1][nt], a[1], b);
      }
    }
  }

  #pragma unroll
  for (int mt=0;mt<2;mt++)
    #pragma unroll
    for (int nt=0;nt<8;nt++){
      int rl  = wr*32 + mt*16 + gr;
      int col = n0 + wc*64 + nt*8 + 2*gc;
      if (MODE == 0){
        int tk0 = s_tk[rl], tk1 = s_tk[rl+8];
        if (tk0 >= 0)
          *(float2*)(g_eo + (size_t)tk0*HH + col) = make_float2(acc[mt][nt][0], acc[mt][nt][1]);
        if (tk1 >= 0)
          *(float2*)(g_eo + (size_t)tk1*HH + col) = make_float2(acc[mt][nt][2], acc[mt][nt][3]);
      } else {
        int t0 = row0 + rl, t1 = t0 + 8;
        float w00 = g_tok_w[t0*2], w01 = g_tok_w[t0*2+1];
        float w10 = g_tok_w[t1*2], w11 = g_tok_w[t1*2+1];
        float2 a0 = *(const float2*)(g_eo + (size_t)(t0*2  )*HH + col);
        float2 b0 = *(const float2*)(g_eo + (size_t)(t0*2+1)*HH + col);
        float2 a1 = *(const float2*)(g_eo + (size_t)(t1*2  )*HH + col);
        float2 b1 = *(const float2*)(g_eo + (size_t)(t1*2+1)*HH + col);
        float2 o0 = make_float2(acc[mt][nt][0] + w00*a0.x + w01*b0.x,
                                acc[mt][nt][1] + w00*a0.y + w01*b0.y);
        float2 o1 = make_float2(acc[mt][nt][2] + w10*a1.x + w11*b1.x,
                                acc[mt][nt][3] + w10*a1.y + w11*b1.y);
        *(float2*)(OutTok + (size_t)t0*HH + col) = o0;
        *(float2*)(OutTok + (size_t)t1*HH + col) = o1;
      }
    }
}

// ---------------- launch ----------------
extern "C" void kernel_launch(void* const* d_in, const int* in_sizes, int n_in,
                              void* d_out, int out_size) {
  const float* x       = (const float*)d_in[0];
  const float* gate_w  = (const float*)d_in[1];
  const float* we_gate = (const float*)d_in[2];
  const float* we_up   = (const float*)d_in[3];
  const float* we_down = (const float*)d_in[4];
  const float* sw_gate = (const float*)d_in[5];
  const float* sw_up   = (const float*)d_in[6];
  const float* sw_down = (const float*)d_in[7];
  float* out = (float*)d_out;

  cudaFuncSetAttribute(gu_mma<true >, cudaFuncAttributeMaxDynamicSharedMemorySize, GU_SMEMB);
  cudaFuncSetAttribute(gu_mma<false>, cudaFuncAttributeMaxDynamicSharedMemorySize, GU_SMEMB);
  cudaFuncSetAttribute(dn_mma<0>,     cudaFuncAttributeMaxDynamicSharedMemorySize, DN_SMEMB);
  cudaFuncSetAttribute(dn_mma<1>,     cudaFuncAttributeMaxDynamicSharedMemorySize, DN_SMEMB);

  route_kernel<<<TT/8, 256>>>(x, gate_w);                 // launch 1
  aux_kernel<<<1, 256>>>();                               // launch 2
  transpose_all<<<dim3(86, 86, 27), dim3(32, 8)>>>(       // launch 3
      we_gate, we_up, we_down, sw_gate, sw_up, sw_down);

  gu_mma<true ><<<dim3(DD/64, ROWCAP/BM), 256, GU_SMEMB>>>();   // launch 4 (profiled)
  gu_mma<false><<<dim3(DD/64, TT/BM),     256, GU_SMEMB>>>();   // launch 5
  dn_mma<0><<<dim3(HH/128, ROWCAP/BM), 256, DN_SMEMB>>>(nullptr);
  dn_mma<1><<<dim3(HH/128, TT/BM),     256, DN_SMEMB>>>(out);
}

// round 12
// speedup vs baseline: 1.0790x; 1.0790x over previous
#include <cuda_runtime.h>
#include <cuda_fp16.h>
#include <cstdint>
#include <math.h>

#define TT 4096
#define HH 1024
#define DD 2752
#define NE 8
#define BM 128
#define ROWCAP (TT*2 + NE*BM)   // 9216

#define NS 3                        // pipeline stages
#define BK 64                       // halfs of K per chunk (128 B rows)
#define A_B (128*128)               // A tile bytes
#define B_B (64*128)                // B tile bytes (gu)
#define GU_STAGEB (A_B + 2*B_B)     // 32768
#define DN_STAGEB (2*A_B)           // 32768
#define GU_SMEMB (NS*GU_STAGEB)     // 98304
#define DN_SMEMB (NS*DN_STAGEB)     // 98304

// ---------------- scratch ----------------
__device__ int    g_offsets[NE+1];
__device__ int    g_row_token[ROWCAP];
__device__ int    g_row_tk[ROWCAP];
__device__ int    g_tok_e[TT*2];
__device__ float  g_tok_w[TT*2];
__device__ __half g_xc [(size_t)TT*HH];      // fp16, k-permuted x
__device__ __half g_wgT[(size_t)NE*DD*HH];   // [D][H], k-permuted on H
__device__ __half g_wuT[(size_t)NE*DD*HH];
__device__ __half g_wdT[(size_t)NE*HH*DD];   // [H][D], k-permuted on D
__device__ __half g_sgT[(size_t)DD*HH];
__device__ __half g_suT[(size_t)DD*HH];
__device__ __half g_sdT[(size_t)HH*DD];
__device__ __half g_hid [(size_t)ROWCAP*DD]; // k-permuted on D
__device__ __half g_shid[(size_t)TT*DD];     // k-permuted on D
__device__ float  g_eo  [(size_t)TT*2*HH];   // plain fp32

// ---------------- helpers ----------------
// permutation within a 16-half group: pairs (p, p+4) become adjacent 4B words
__device__ __forceinline__ int phys16(int j){
  int p = j>>1, b = j&1;
  return 4*(p&3) + 2*(p>>2) + b;
}
__device__ __forceinline__ uint32_t s2u(const void* p){
  uint32_t a; asm("{ .reg .u64 t; cvta.to.shared.u64 t, %1; cvt.u32.u64 %0, t; }":"=r"(a):"l"(p)); return a;
}
__device__ __forceinline__ void cpa16(uint32_t d, const void* s){
  asm volatile("cp.async.cg.shared.global [%0], [%1], 16;"::"r"(d),"l"(s));
}
__device__ __forceinline__ void cpcommit(){ asm volatile("cp.async.commit_group;"); }
__device__ __forceinline__ void cpwait(int allow){
  if (allow <= 0) asm volatile("cp.async.wait_group 0;");
  else            asm volatile("cp.async.wait_group 1;");
}
__device__ __forceinline__ void mma16(float* c, const uint32_t* a, const uint32_t* b){
  asm volatile("mma.sync.aligned.m16n8k16.row.col.f32.f16.f16.f32 "
    "{%0,%1,%2,%3},{%4,%5,%6,%7},{%8,%9},{%0,%1,%2,%3};"
    : "+f"(c[0]),"+f"(c[1]),"+f"(c[2]),"+f"(c[3])
    : "r"(a[0]),"r"(a[1]),"r"(a[2]),"r"(a[3]),"r"(b[0]),"r"(b[1]));
}

// ---------------- route: logits/softmax/top2 + fp16-permuted x copy ----------------
__global__ void route_kernel(const float* __restrict__ x, const float* __restrict__ gw){
  int t = blockIdx.x*(blockDim.x>>5) + (threadIdx.x>>5);
  int lane = threadIdx.x & 31;
  if (t >= TT) return;
  const float* xr = x + (size_t)t*HH;
  float xs[HH/32];
  #pragma unroll
  for (int i=0;i<HH/32;i++) xs[i] = xr[lane+32*i];

  // fp16, k-permuted copy: k = lane + 32*i; group base = (lane&16) + 32*i
  int dpos = (lane & 16) + phys16(lane & 15);
  __half* xo = g_xc + (size_t)t*HH;
  #pragma unroll
  for (int i=0;i<HH/32;i++) xo[dpos + 32*i] = __float2half(xs[i]);

  float logit[NE];
  #pragma unroll
  for (int e=0;e<NE;e++){
    const float* w = gw + e*HH;
    float s = 0.f;
    #pragma unroll
    for (int i=0;i<HH/32;i++) s += xs[i]*w[lane+32*i];
    #pragma unroll
    for (int o=16;o;o>>=1) s += __shfl_xor_sync(0xffffffffu, s, o);
    logit[e] = s;
  }
  float m = logit[0];
  #pragma unroll
  for (int e=1;e<NE;e++) m = fmaxf(m, logit[e]);
  float p[NE], ssum = 0.f;
  #pragma unroll
  for (int e=0;e<NE;e++){ p[e] = expf(logit[e]-m); ssum += p[e]; }
  float inv = 1.f/ssum;
  #pragma unroll
  for (int e=0;e<NE;e++) p[e] *= inv;
  int i0 = 0;
  #pragma unroll
  for (int e=1;e<NE;e++) if (p[e] > p[i0]) i0 = e;
  int i1 = -1;
  #pragma unroll
  for (int e=0;e<NE;e++) if (e != i0 && (i1 < 0 || p[e] > p[i1])) i1 = e;
  float w0 = p[i0], w1 = p[i1];
  float nrm = 1.f/(w0+w1+1e-20f);
  if (lane == 0){
    g_tok_e[t*2] = i0; g_tok_e[t*2+1] = i1;
    g_tok_w[t*2] = w0*nrm; g_tok_w[t*2+1] = w1*nrm;
  }
}

// ---------------- aux: count + scan + init + assign (single block) ----------------
__global__ void aux_kernel(){
  __shared__ int sc[NE], so[NE+1], scur[NE];
  int tid = threadIdx.x;
  if (tid < NE){ sc[tid] = 0; scur[tid] = 0; }
  __syncthreads();
  for (int i = tid; i < TT*2; i += 256) atomicAdd(&sc[g_tok_e[i]], 1);
  __syncthreads();
  if (tid == 0){
    int off = 0;
    for (int e=0;e<NE;e++){ so[e]=off; off += ((sc[e]+BM-1)/BM)*BM; }
    so[NE] = off;
  }
  __syncthreads();
  if (tid <= NE) g_offsets[tid] = so[tid];
  for (int i = tid; i < ROWCAP; i += 256) g_row_token[i] = -1;
  __syncthreads();
  for (int i = tid; i < TT*2; i += 256){
    int e = g_tok_e[i];
    int pos = atomicAdd(&scur[e], 1);
    int row = so[e] + pos;
    g_row_token[row] = i>>1;
    g_row_tk[row] = i;
  }
}

// ---------------- fused weight transpose -> fp16 + k-permute ----------------
__global__ void transpose_all(const float* __restrict__ wg, const float* __restrict__ wu,
                              const float* __restrict__ wd, const float* __restrict__ sg,
                              const float* __restrict__ su, const float* __restrict__ sd){
  int z = blockIdx.z;
  const float* src; __half* dst; int R, C;
  if (z < 8)       { src = wg + (size_t)z*HH*DD;      dst = g_wgT + (size_t)z*DD*HH;      R=HH; C=DD; }
  else if (z < 16) { src = wu + (size_t)(z-8)*HH*DD;  dst = g_wuT + (size_t)(z-8)*DD*HH;  R=HH; C=DD; }
  else if (z < 24) { src = wd + (size_t)(z-16)*DD*HH; dst = g_wdT + (size_t)(z-16)*HH*DD; R=DD; C=HH; }
  else if (z==24)  { src = sg; dst = g_sgT; R=HH; C=DD; }
  else if (z==25)  { src = su; dst = g_suT; R=HH; C=DD; }
  else             { src = sd; dst = g_sdT; R=DD; C=HH; }
  if (blockIdx.x*32 >= C || blockIdx.y*32 >= R) return;

  __shared__ float t[32][33];
  int x = blockIdx.x*32 + threadIdx.x;
  int y0 = blockIdx.y*32;
  #pragma unroll
  for (int j=0;j<32;j+=8)
    t[threadIdx.y+j][threadIdx.x] = src[(size_t)(y0+threadIdx.y+j)*C + x];
  __syncthreads();
  int xxl = blockIdx.y*32 + threadIdx.x;            // logical k index
  int xx  = (xxl & ~15) | phys16(xxl & 15);         // physical (k-pair-permuted)
  int yy0 = blockIdx.x*32;
  #pragma unroll
  for (int j=0;j<32;j+=8)
    dst[(size_t)(yy0+threadIdx.y+j)*R + xx] = __float2half(t[threadIdx.x][threadIdx.y+j]);
}

// ---------------- gate+up GEMM: 128x64 tile, fp16 mma, dual-B, fused silu ----------------
template<bool ROUTED>
__global__ void __launch_bounds__(256,2) gu_mma(){
  extern __shared__ char smc[];
  __half* sm = (__half*)smc;
  __shared__ int rtok[BM];
  const int tid = threadIdx.x, lane = tid&31, wid = tid>>5;
  const int wr = wid>>1, wc = wid&1;
  const int gr = lane>>2, gc = lane&3;
  const int row0 = blockIdx.y*BM, n0 = blockIdx.x*64;
  if (ROUTED && row0 >= g_offsets[NE]) return;

  const __half *Wg, *Wu; __half* Out;
  if (ROUTED){
    int e = 0;
    #pragma unroll
    for (int i=1;i<NE;i++) if (row0 >= g_offsets[i]) e = i;
    Wg = g_wgT + (size_t)e*DD*HH;
    Wu = g_wuT + (size_t)e*DD*HH;
    Out = g_hid;
  } else { Wg = g_sgT; Wu = g_suT; Out = g_shid; }

  if (tid < BM){
    int t = ROUTED ? g_row_token[row0+tid] : (row0+tid);
    rtok[tid] = t < 0 ? 0 : t;
  }
  __syncthreads();

  const int NCH = HH/BK;   // 16
  auto ld = [&](int c, int s){
    uint32_t sA = s2u(smc + s*GU_STAGEB);
    uint32_t sG = sA + A_B;
    uint32_t sU = sG + B_B;
    int k0 = c*BK;
    #pragma unroll
    for (int j=0;j<4;j++){
      int q = tid + 256*j, r = q>>3, sg = q&7;
      cpa16(sA + r*128 + 16*(sg ^ (r&7)), g_xc + (size_t)rtok[r]*HH + k0 + sg*8);
    }
    #pragma unroll
    for (int j=0;j<2;j++){
      int q = tid + 256*j, r = q>>3, sg = q&7;
      uint32_t so = r*128 + 16*(sg ^ (r&7));
      cpa16(sG + so, Wg + (size_t)(n0+r)*HH + k0 + sg*8);
      cpa16(sU + so, Wu + (size_t)(n0+r)*HH + k0 + sg*8);
    }
    cpcommit();
  };
  ld(0,0); ld(1,1);

  float accg[2][4][4], accu[2][4][4];
  #pragma unroll
  for (int a=0;a<2;a++)
    #pragma unroll
    for (int b=0;b<4;b++)
      #pragma unroll
      for (int d=0;d<4;d++){ accg[a][b][d]=0.f; accu[a][b][d]=0.f; }

  for (int c=0;c<NCH;c++){
    cpwait(NCH-1-c < 1 ? 0 : 1);
    __syncthreads();
    if (c+2 < NCH) ld(c+2, (c+2)%NS);
    const __half* As = sm + (c%NS)*(GU_STAGEB/2);
    const __half* Bg = As + A_B/2;
    const __half* Bu = Bg + B_B/2;
    #pragma unroll
    for (int ks=0;ks<4;ks++){
      int kb = 8*((2*ks + (gc>>1)) ^ gr) + 4*(gc&1);   // half offset in 64-half row
      uint32_t a[2][4];
      #pragma unroll
      for (int mt=0;mt<2;mt++){
        int r0 = wr*32 + mt*16;
        uint2 lo = *(const uint2*)(As + (r0+gr  )*64 + kb);
        uint2 hi = *(const uint2*)(As + (r0+gr+8)*64 + kb);
        a[mt][0] = lo.x; a[mt][1] = hi.x; a[mt][2] = lo.y; a[mt][3] = hi.y;
      }
      #pragma unroll
      for (int nt=0;nt<4;nt++){
        int n = wc*32 + nt*8 + gr;
        uint2 vg = *(const uint2*)(Bg + n*64 + kb);
        uint2 vu = *(const uint2*)(Bu + n*64 + kb);
        uint32_t bg[2] = { vg.x, vg.y };
        uint32_t bu[2] = { vu.x, vu.y };
        mma16(accg[0][nt], a[0], bg);
        mma16(accg[1][nt], a[1], bg);
        mma16(accu[0][nt], a[0], bu);
        mma16(accu[1][nt], a[1], bu);
      }
    }
  }

  // epilogue: silu(g)*u -> fp16, stored with D k-pair-permutation (feeds dn GEMM)
  #pragma unroll
  for (int mt=0;mt<2;mt++)
    #pragma unroll
    for (int nt=0;nt<4;nt++){
      int r  = row0 + wr*32 + mt*16 + gr;
      // cols 2gc,2gc+1 of block wc*32+nt*8 -> phys half offset in 16-group
      int grp = n0 + wc*32 + (nt>>1)*16 + 4*gc + 2*(nt&1);
      float g0 = accg[mt][nt][0], u0 = accu[mt][nt][0];
      float g1 = accg[mt][nt][1], u1 = accu[mt][nt][1];
      float g2 = accg[mt][nt][2], u2 = accu[mt][nt][2];
      float g3 = accg[mt][nt][3], u3 = accu[mt][nt][3];
      *(half2*)(Out + (size_t)r*DD + grp) =
          __floats2half2_rn(g0/(1.f+expf(-g0))*u0, g1/(1.f+expf(-g1))*u1);
      *(half2*)(Out + (size_t)(r+8)*DD + grp) =
          __floats2half2_rn(g2/(1.f+expf(-g2))*u2, g3/(1.f+expf(-g3))*u3);
    }
}

// ---------------- down GEMM: 128x128 tile, fp16 mma ----------------
template<int MODE>
__global__ void __launch_bounds__(256,2) dn_mma(float* __restrict__ OutTok){
  extern __shared__ char smc[];
  __half* sm = (__half*)smc;
  __shared__ int s_tk[BM];
  const int tid = threadIdx.x, lane = tid&31, wid = tid>>5;
  const int wr = wid>>1, wc = wid&1;
  const int gr = lane>>2, gc = lane&3;
  const int row0 = blockIdx.y*BM, n0 = blockIdx.x*128;
  if (MODE==0 && row0 >= g_offsets[NE]) return;

  const __half *A, *Wd;
  if (MODE == 0){
    int e = 0;
    #pragma unroll
    for (int i=1;i<NE;i++) if (row0 >= g_offsets[i]) e = i;
    Wd = g_wdT + (size_t)e*HH*DD;
    A = g_hid;
  } else { Wd = g_sdT; A = g_shid; }

  if (tid < BM)
    s_tk[tid] = (MODE==0) ? ((g_row_token[row0+tid] < 0) ? -1 : g_row_tk[row0+tid]) : 0;
  __syncthreads();

  const int NCH = DD/BK;   // 43
  auto ld = [&](int c, int s){
    uint32_t sA = s2u(smc + s*DN_STAGEB);
    uint32_t sB = sA + A_B;
    int k0 = c*BK;
    #pragma unroll
    for (int j=0;j<4;j++){
      int q = tid + 256*j, r = q>>3, sg = q&7;
      uint32_t so = r*128 + 16*(sg ^ (r&7));
      cpa16(sA + so, A  + (size_t)(row0+r)*DD + k0 + sg*8);
      cpa16(sB + so, Wd + (size_t)(n0 +r)*DD + k0 + sg*8);
    }
    cpcommit();
  };
  ld(0,0); ld(1,1);

  float acc[2][8][4];
  #pragma unroll
  for (int a=0;a<2;a++)
    #pragma unroll
    for (int b=0;b<8;b++)
      #pragma unroll
      for (int d=0;d<4;d++) acc[a][b][d]=0.f;

  for (int c=0;c<NCH;c++){
    cpwait(NCH-1-c < 1 ? 0 : 1);
    __syncthreads();
    if (c+2 < NCH) ld(c+2, (c+2)%NS);
    const __half* As = sm + (c%NS)*(DN_STAGEB/2);
    const __half* Bs = As + A_B/2;
    #pragma unroll
    for (int ks=0;ks<4;ks++){
      int kb = 8*((2*ks + (gc>>1)) ^ gr) + 4*(gc&1);
      uint32_t a[2][4];
      #pragma unroll
      for (int mt=0;mt<2;mt++){
        int r0 = wr*32 + mt*16;
        uint2 lo = *(const uint2*)(As + (r0+gr  )*64 + kb);
        uint2 hi = *(const uint2*)(As + (r0+gr+8)*64 + kb);
        a[mt][0] = lo.x; a[mt][1] = hi.x; a[mt][2] = lo.y; a[mt][3] = hi.y;
      }
      #pragma unroll
      for (int nt=0;nt<8;nt++){
        int n = wc*64 + nt*8 + gr;
        uint2 vb = *(const uint2*)(Bs + n*64 + kb);
        uint32_t b[2] = { vb.x, vb.y };
        mma16(acc[0][nt], a[0], b);
        mma16(acc[1][nt], a[1], b);
      }
    }
  }

  #pragma unroll
  for (int mt=0;mt<2;mt++)
    #pragma unroll
    for (int nt=0;nt<8;nt++){
      int rl  = wr*32 + mt*16 + gr;
      int col = n0 + wc*64 + nt*8 + 2*gc;
      if (MODE == 0){
        int tk0 = s_tk[rl], tk1 = s_tk[rl+8];
        if (tk0 >= 0)
          *(float2*)(g_eo + (size_t)tk0*HH + col) = make_float2(acc[mt][nt][0], acc[mt][nt][1]);
        if (tk1 >= 0)
          *(float2*)(g_eo + (size_t)tk1*HH + col) = make_float2(acc[mt][nt][2], acc[mt][nt][3]);
      } else {
        int t0 = row0 + rl, t1 = t0 + 8;
        float w00 = g_tok_w[t0*2], w01 = g_tok_w[t0*2+1];
        float w10 = g_tok_w[t1*2], w11 = g_tok_w[t1*2+1];
        float2 a0 = *(const float2*)(g_eo + (size_t)(t0*2  )*HH + col);
        float2 b0 = *(const float2*)(g_eo + (size_t)(t0*2+1)*HH + col);
        float2 a1 = *(const float2*)(g_eo + (size_t)(t1*2  )*HH + col);
        float2 b1 = *(const float2*)(g_eo + (size_t)(t1*2+1)*HH + col);
        float2 o0 = make_float2(acc[mt][nt][0] + w00*a0.x + w01*b0.x,
                                acc[mt][nt][1] + w00*a0.y + w01*b0.y);
        float2 o1 = make_float2(acc[mt][nt][2] + w10*a1.x + w11*b1.x,
                                acc[mt][nt][3] + w10*a1.y + w11*b1.y);
        *(float2*)(OutTok + (size_t)t0*HH + col) = o0;
        *(float2*)(OutTok + (size_t)t1*HH + col) = o1;
      }
    }
}

// ---------------- launch ----------------
extern "C" void kernel_launch(void* const* d_in, const int* in_sizes, int n_in,
                              void* d_out, int out_size) {
  const float* x       = (const float*)d_in[0];
  const float* gate_w  = (const float*)d_in[1];
  const float* we_gate = (const float*)d_in[2];
  const float* we_up   = (const float*)d_in[3];
  const float* we_down = (const float*)d_in[4];
  const float* sw_gate = (const float*)d_in[5];
  const float* sw_up   = (const float*)d_in[6];
  const float* sw_down = (const float*)d_in[7];
  float* out = (float*)d_out;

  cudaFuncSetAttribute(gu_mma<true >, cudaFuncAttributeMaxDynamicSharedMemorySize, GU_SMEMB);
  cudaFuncSetAttribute(gu_mma<false>, cudaFuncAttributeMaxDynamicSharedMemorySize, GU_SMEMB);
  cudaFuncSetAttribute(dn_mma<0>,     cudaFuncAttributeMaxDynamicSharedMemorySize, DN_SMEMB);
  cudaFuncSetAttribute(dn_mma<1>,     cudaFuncAttributeMaxDynamicSharedMemorySize, DN_SMEMB);

  route_kernel<<<TT/8, 256>>>(x, gate_w);                 // launch 1
  aux_kernel<<<1, 256>>>();                               // launch 2
  transpose_all<<<dim3(86, 86, 27), dim3(32, 8)>>>(       // launch 3
      we_gate, we_up, we_down, sw_gate, sw_up, sw_down);

  gu_mma<true ><<<dim3(DD/64, ROWCAP/BM), 256, GU_SMEMB>>>();   // launch 4 (profiled)
  gu_mma<false><<<dim3(DD/64, TT/BM),     256, GU_SMEMB>>>();
  dn_mma<0><<<dim3(HH/128, ROWCAP/BM), 256, DN_SMEMB>>>(nullptr);
  dn_mma<1><<<dim3(HH/128, TT/BM),     256, DN_SMEMB>>>(out);
}